// round 11
// baseline (speedup 1.0000x reference)
#include <cuda_runtime.h>
#include <cstdint>

#define E_EDGES     300000
#define NATOMS      10000
#define NATOMS_PAD  10016
#define CCH         256
#define RBFD        16
#define ROWS        32
#define WS_STRIDE   66

// Per-atom accumulator scratch (padded rows stay zero so the last MLP block reads zeros)
__device__ float g_accum[NATOMS_PAD * CCH];

__device__ __forceinline__ unsigned long long fma2(unsigned long long a,
                                                   unsigned long long b,
                                                   unsigned long long c) {
    unsigned long long d;
    asm("fma.rn.f32x2 %0, %1, %2, %3;" : "=l"(d) : "l"(a), "l"(b), "l"(c));
    return d;
}

__device__ __forceinline__ float hadd2(unsigned long long a) {
    float lo, hi;
    asm("mov.b64 {%0, %1}, %2;" : "=f"(lo), "=f"(hi) : "l"(a));
    return lo + hi;
}

// ---------------------------------------------------------------------------
// Kernel 0: zero the accumulator
// ---------------------------------------------------------------------------
__global__ void zero_kernel() {
    int i = blockIdx.x * blockDim.x + threadIdx.x;
    const int n4 = NATOMS_PAD * CCH / 4;
    float4* p = reinterpret_cast<float4*>(g_accum);
    if (i < n4) p[i] = make_float4(0.f, 0.f, 0.f, 0.f);
}

// ---------------------------------------------------------------------------
// Kernel 1: fused rbf-filter * x  +  scatter-add (red.v4.f32)
// Block = 256 threads = 4 edge-lanes (ey) x 64 channel-groups (cx, 4 ch each).
// W rows for this thread's 4 channels live in registers as f32x2 pairs.
// Edge index is read as INT32 (JAX without x64 downcasts int64 -> int32).
// ---------------------------------------------------------------------------
__global__ void __launch_bounds__(256) scatter_kernel(
    const float* __restrict__ x, const float* __restrict__ rbf,
    const int* __restrict__ eidx,
    const float* __restrict__ w_rbf, const float* __restrict__ b_rbf, int nE)
{
    const int tid = threadIdx.x;
    const int cx  = tid & 63;
    const int ey  = tid >> 6;
    const int c0  = cx * 4;

    // Load w_rbf rows for 4 channels as 8 f32x2 pairs each (pairs over RBF dim)
    unsigned long long w2[4][8];
#pragma unroll
    for (int j = 0; j < 4; j++) {
        const ulonglong2* wp = reinterpret_cast<const ulonglong2*>(w_rbf + (c0 + j) * RBFD);
        ulonglong2 q0 = wp[0], q1 = wp[1], q2 = wp[2], q3 = wp[3];
        w2[j][0] = q0.x; w2[j][1] = q0.y; w2[j][2] = q1.x; w2[j][3] = q1.y;
        w2[j][4] = q2.x; w2[j][5] = q2.y; w2[j][6] = q3.x; w2[j][7] = q3.y;
    }
    const float4 bv = *reinterpret_cast<const float4*>(b_rbf + c0);

    const int stride = gridDim.x * 4;
    for (int e = blockIdx.x * 4 + ey; e < nE; e += stride) {
        const int a = eidx[e];

        // rbf row: 16 floats = 8 f32x2 pairs (broadcast load across the 64 cx threads)
        const ulonglong2* rp = reinterpret_cast<const ulonglong2*>(rbf + (size_t)e * RBFD);
        ulonglong2 r0 = rp[0], r1 = rp[1], r2 = rp[2], r3 = rp[3];
        unsigned long long rf2[8] = {r0.x, r0.y, r1.x, r1.y, r2.x, r2.y, r3.x, r3.y};

        const float4 xv = *reinterpret_cast<const float4*>(x + (size_t)e * CCH + c0);

        unsigned long long a0 = 0ull, a1 = 0ull, a2 = 0ull, a3 = 0ull;
#pragma unroll
        for (int r = 0; r < 8; r++) {
            a0 = fma2(w2[0][r], rf2[r], a0);
            a1 = fma2(w2[1][r], rf2[r], a1);
            a2 = fma2(w2[2][r], rf2[r], a2);
            a3 = fma2(w2[3][r], rf2[r], a3);
        }
        const float m0 = (hadd2(a0) + bv.x) * xv.x;
        const float m1 = (hadd2(a1) + bv.y) * xv.y;
        const float m2 = (hadd2(a2) + bv.z) * xv.z;
        const float m3 = (hadd2(a3) + bv.w) * xv.w;

        if (a >= 0 && a < NATOMS) {   // defensive: never fault, surface rel_err instead
            float* dst = g_accum + (size_t)a * CCH + c0;
            asm volatile("red.global.add.v4.f32 [%0], {%1, %2, %3, %4};"
                         :: "l"(dst), "f"(m0), "f"(m1), "f"(m2), "f"(m3) : "memory");
        }
    }
}

// ---------------------------------------------------------------------------
// Kernel 2: fused 3-layer MLP. One block = 32 rows x 256 cols.
// Thread owns one output column; accumulates 32 rows with f32x2 over K-pairs.
// Weight k-tiles staged through smem (stride 66 -> 8B aligned, <=2-way conflict).
// h1/h2 live in smem (a_s is reused in place).
// ---------------------------------------------------------------------------
__device__ __forceinline__ void gemm_silu_layer(
    float* a_s, float* ws,
    const float* __restrict__ wglob, const float* __restrict__ bias, int c)
{
    unsigned long long acc[ROWS];
#pragma unroll
    for (int m = 0; m < ROWS; m++) acc[m] = 0ull;

    const int tid = threadIdx.x;
    for (int kt = 0; kt < 4; kt++) {
        __syncthreads();
        {   // stage W tile [256 x 64] -> ws[cr*66 + kk]
            const int cr0 = tid >> 4;
            const int kk4 = (tid & 15) << 2;
#pragma unroll
            for (int p = 0; p < 16; p++) {
                const int cr = cr0 + p * 16;
                const float4 v = *reinterpret_cast<const float4*>(wglob + cr * 256 + kt * 64 + kk4);
                float* d = ws + cr * WS_STRIDE + kk4;
                d[0] = v.x; d[1] = v.y; d[2] = v.z; d[3] = v.w;
            }
        }
        __syncthreads();

        const float* abase0 = a_s + kt * 64;
#pragma unroll 1
        for (int k2 = 0; k2 < 32; k2++) {
            const unsigned long long wp =
                *reinterpret_cast<const unsigned long long*>(ws + c * WS_STRIDE + 2 * k2);
            const float* ab = abase0 + 2 * k2;
#pragma unroll
            for (int m = 0; m < ROWS; m++) {
                const unsigned long long ap =
                    *reinterpret_cast<const unsigned long long*>(ab + m * 256);
                acc[m] = fma2(wp, ap, acc[m]);
            }
        }
    }
    __syncthreads();  // all reads of a_s / ws done before overwriting a_s

    const float bc = bias[c];
#pragma unroll
    for (int m = 0; m < ROWS; m++) {
        float v = hadd2(acc[m]) + bc;
        v = v / (1.0f + __expf(-v));   // SiLU
        a_s[m * 256 + c] = v;
    }
}

__global__ void __launch_bounds__(256) mlp_kernel(
    const float* __restrict__ w1, const float* __restrict__ b1,
    const float* __restrict__ w2, const float* __restrict__ b2,
    const float* __restrict__ w3, const float* __restrict__ b3,
    float* __restrict__ out)
{
    extern __shared__ float smem[];
    float* a_s = smem;                 // 32*256 floats
    float* ws  = smem + ROWS * 256;    // 256*66 floats

    const int tid  = threadIdx.x;
    const int row0 = blockIdx.x * ROWS;

    // stage input rows (padded accumulator rows are zero)
    {
        const float4* src = reinterpret_cast<const float4*>(g_accum + (size_t)row0 * 256);
        float4* dst = reinterpret_cast<float4*>(a_s);
#pragma unroll
        for (int i = 0; i < 8; i++) dst[i * 256 + tid] = src[i * 256 + tid];
    }
    // gemm_silu_layer starts with __syncthreads(), covering the staging barrier.
    gemm_silu_layer(a_s, ws, w1, b1, tid);
    gemm_silu_layer(a_s, ws, w2, b2, tid);

    // layer 3: y[m] = dot(h2[m,:], w3) + b3
    const float w3c = w3[tid];
    float* red = ws;                   // ws reads are done (sync inside layer 2)
    const int lane = tid & 31, wid = tid >> 5;
#pragma unroll
    for (int m = 0; m < ROWS; m++) {
        float v = a_s[m * 256 + tid] * w3c;   // own column: no race
#pragma unroll
        for (int off = 16; off; off >>= 1) v += __shfl_down_sync(0xFFFFFFFFu, v, off);
        if (lane == 0) red[m * 8 + wid] = v;
    }
    __syncthreads();
    if (tid < ROWS) {
        float s = b3[0];
#pragma unroll
        for (int w = 0; w < 8; w++) s += red[tid * 8 + w];
        const int row = row0 + tid;
        if (row < NATOMS) out[row] = s;
    }
}

// ---------------------------------------------------------------------------
extern "C" void kernel_launch(void* const* d_in, const int* in_sizes, int n_in,
                              void* d_out, int out_size)
{
    const float* x   = (const float*)d_in[0];
    const float* rbf = (const float*)d_in[1];
    const int    nE  = in_sizes[0] / CCH;

    // `num_atoms` is a bare Python int in the reference; it may or may not be
    // materialized as a device input. Detect via element count (scalar == 1).
    int p = 2;
    if (in_sizes[2] == 1) p = 3;           // skip num_atoms scalar if present

    const int*   eidx  = (const int*)d_in[p + 0];   // int32 (JAX x64 disabled)
    const float* w_rbf = (const float*)d_in[p + 1];
    const float* b_rbf = (const float*)d_in[p + 2];
    const float* w1    = (const float*)d_in[p + 3];
    const float* b1    = (const float*)d_in[p + 4];
    const float* w2    = (const float*)d_in[p + 5];
    const float* b2    = (const float*)d_in[p + 6];
    const float* w3    = (const float*)d_in[p + 7];
    const float* b3    = (const float*)d_in[p + 8];
    float*       out   = (float*)d_out;

    const int n4 = NATOMS_PAD * CCH / 4;
    zero_kernel<<<(n4 + 255) / 256, 256>>>();

    scatter_kernel<<<1184, 256>>>(x, rbf, eidx, w_rbf, b_rbf, nE);

    const size_t smem_bytes = (size_t)(ROWS * 256 + 256 * WS_STRIDE) * sizeof(float); // ~100 KB
    cudaFuncSetAttribute(mlp_kernel, cudaFuncAttributeMaxDynamicSharedMemorySize,
                         (int)smem_bytes);
    mlp_kernel<<<NATOMS_PAD / ROWS, 256, smem_bytes>>>(w1, b1, w2, b2, w3, b3, out);
}

// round 12
// speedup vs baseline: 1.0001x; 1.0001x over previous
#include <cuda_runtime.h>
#include <cstdint>

#define E_EDGES     300000
#define NATOMS      10000
#define NATOMS_PAD  10016
#define CCH         256
#define RBFD        16
#define ROWS        32
#define WS_STRIDE   66

// Per-atom accumulator scratch (padded rows stay zero so the last MLP block reads zeros)
__device__ float g_accum[NATOMS_PAD * CCH];

__device__ __forceinline__ unsigned long long fma2(unsigned long long a,
                                                   unsigned long long b,
                                                   unsigned long long c) {
    unsigned long long d;
    asm("fma.rn.f32x2 %0, %1, %2, %3;" : "=l"(d) : "l"(a), "l"(b), "l"(c));
    return d;
}

__device__ __forceinline__ float hadd2(unsigned long long a) {
    float lo, hi;
    asm("mov.b64 {%0, %1}, %2;" : "=f"(lo), "=f"(hi) : "l"(a));
    return lo + hi;
}

// ---------------------------------------------------------------------------
// Kernel 0: zero the accumulator
// ---------------------------------------------------------------------------
__global__ void zero_kernel() {
    int i = blockIdx.x * blockDim.x + threadIdx.x;
    const int n4 = NATOMS_PAD * CCH / 4;
    float4* p = reinterpret_cast<float4*>(g_accum);
    if (i < n4) p[i] = make_float4(0.f, 0.f, 0.f, 0.f);
}

// ---------------------------------------------------------------------------
// Kernel 1: fused rbf-filter * x  +  scatter-add (red.v4.f32)
// Block = 256 threads = 4 edge-lanes (ey) x 64 channel-groups (cx, 4 ch each).
// W rows for this thread's 4 channels live in registers as f32x2 pairs.
// Edge index is read as INT32 (JAX without x64 downcasts int64 -> int32).
// ---------------------------------------------------------------------------
__global__ void __launch_bounds__(256) scatter_kernel(
    const float* __restrict__ x, const float* __restrict__ rbf,
    const int* __restrict__ eidx,
    const float* __restrict__ w_rbf, const float* __restrict__ b_rbf, int nE)
{
    const int tid = threadIdx.x;
    const int cx  = tid & 63;
    const int ey  = tid >> 6;
    const int c0  = cx * 4;

    // Load w_rbf rows for 4 channels as 8 f32x2 pairs each (pairs over RBF dim)
    unsigned long long w2[4][8];
#pragma unroll
    for (int j = 0; j < 4; j++) {
        const ulonglong2* wp = reinterpret_cast<const ulonglong2*>(w_rbf + (c0 + j) * RBFD);
        ulonglong2 q0 = wp[0], q1 = wp[1], q2 = wp[2], q3 = wp[3];
        w2[j][0] = q0.x; w2[j][1] = q0.y; w2[j][2] = q1.x; w2[j][3] = q1.y;
        w2[j][4] = q2.x; w2[j][5] = q2.y; w2[j][6] = q3.x; w2[j][7] = q3.y;
    }
    const float4 bv = *reinterpret_cast<const float4*>(b_rbf + c0);

    const int stride = gridDim.x * 4;
    for (int e = blockIdx.x * 4 + ey; e < nE; e += stride) {
        const int a = eidx[e];

        // rbf row: 16 floats = 8 f32x2 pairs (broadcast load across the 64 cx threads)
        const ulonglong2* rp = reinterpret_cast<const ulonglong2*>(rbf + (size_t)e * RBFD);
        ulonglong2 r0 = rp[0], r1 = rp[1], r2 = rp[2], r3 = rp[3];
        unsigned long long rf2[8] = {r0.x, r0.y, r1.x, r1.y, r2.x, r2.y, r3.x, r3.y};

        const float4 xv = *reinterpret_cast<const float4*>(x + (size_t)e * CCH + c0);

        unsigned long long a0 = 0ull, a1 = 0ull, a2 = 0ull, a3 = 0ull;
#pragma unroll
        for (int r = 0; r < 8; r++) {
            a0 = fma2(w2[0][r], rf2[r], a0);
            a1 = fma2(w2[1][r], rf2[r], a1);
            a2 = fma2(w2[2][r], rf2[r], a2);
            a3 = fma2(w2[3][r], rf2[r], a3);
        }
        const float m0 = (hadd2(a0) + bv.x) * xv.x;
        const float m1 = (hadd2(a1) + bv.y) * xv.y;
        const float m2 = (hadd2(a2) + bv.z) * xv.z;
        const float m3 = (hadd2(a3) + bv.w) * xv.w;

        if (a >= 0 && a < NATOMS) {   // defensive: never fault, surface rel_err instead
            float* dst = g_accum + (size_t)a * CCH + c0;
            asm volatile("red.global.add.v4.f32 [%0], {%1, %2, %3, %4};"
                         :: "l"(dst), "f"(m0), "f"(m1), "f"(m2), "f"(m3) : "memory");
        }
    }
}

// ---------------------------------------------------------------------------
// Kernel 2: fused 3-layer MLP. One block = 32 rows x 256 cols.
// Thread owns one output column; accumulates 32 rows with f32x2 over K-pairs.
// Weight k-tiles staged through smem (stride 66 -> 8B aligned, <=2-way conflict).
// h1/h2 live in smem (a_s is reused in place).
// ---------------------------------------------------------------------------
__device__ __forceinline__ void gemm_silu_layer(
    float* a_s, float* ws,
    const float* __restrict__ wglob, const float* __restrict__ bias, int c)
{
    unsigned long long acc[ROWS];
#pragma unroll
    for (int m = 0; m < ROWS; m++) acc[m] = 0ull;

    const int tid = threadIdx.x;
    for (int kt = 0; kt < 4; kt++) {
        __syncthreads();
        {   // stage W tile [256 x 64] -> ws[cr*66 + kk]
            const int cr0 = tid >> 4;
            const int kk4 = (tid & 15) << 2;
#pragma unroll
            for (int p = 0; p < 16; p++) {
                const int cr = cr0 + p * 16;
                const float4 v = *reinterpret_cast<const float4*>(wglob + cr * 256 + kt * 64 + kk4);
                float* d = ws + cr * WS_STRIDE + kk4;
                d[0] = v.x; d[1] = v.y; d[2] = v.z; d[3] = v.w;
            }
        }
        __syncthreads();

        const float* abase0 = a_s + kt * 64;
#pragma unroll 1
        for (int k2 = 0; k2 < 32; k2++) {
            const unsigned long long wp =
                *reinterpret_cast<const unsigned long long*>(ws + c * WS_STRIDE + 2 * k2);
            const float* ab = abase0 + 2 * k2;
#pragma unroll
            for (int m = 0; m < ROWS; m++) {
                const unsigned long long ap =
                    *reinterpret_cast<const unsigned long long*>(ab + m * 256);
                acc[m] = fma2(wp, ap, acc[m]);
            }
        }
    }
    __syncthreads();  // all reads of a_s / ws done before overwriting a_s

    const float bc = bias[c];
#pragma unroll
    for (int m = 0; m < ROWS; m++) {
        float v = hadd2(acc[m]) + bc;
        v = v / (1.0f + __expf(-v));   // SiLU
        a_s[m * 256 + c] = v;
    }
}

__global__ void __launch_bounds__(256) mlp_kernel(
    const float* __restrict__ w1, const float* __restrict__ b1,
    const float* __restrict__ w2, const float* __restrict__ b2,
    const float* __restrict__ w3, const float* __restrict__ b3,
    float* __restrict__ out)
{
    extern __shared__ float smem[];
    float* a_s = smem;                 // 32*256 floats
    float* ws  = smem + ROWS * 256;    // 256*66 floats

    const int tid  = threadIdx.x;
    const int row0 = blockIdx.x * ROWS;

    // stage input rows (padded accumulator rows are zero)
    {
        const float4* src = reinterpret_cast<const float4*>(g_accum + (size_t)row0 * 256);
        float4* dst = reinterpret_cast<float4*>(a_s);
#pragma unroll
        for (int i = 0; i < 8; i++) dst[i * 256 + tid] = src[i * 256 + tid];
    }
    // gemm_silu_layer starts with __syncthreads(), covering the staging barrier.
    gemm_silu_layer(a_s, ws, w1, b1, tid);
    gemm_silu_layer(a_s, ws, w2, b2, tid);

    // layer 3: y[m] = dot(h2[m,:], w3) + b3
    const float w3c = w3[tid];
    float* red = ws;                   // ws reads are done (sync inside layer 2)
    const int lane = tid & 31, wid = tid >> 5;
#pragma unroll
    for (int m = 0; m < ROWS; m++) {
        float v = a_s[m * 256 + tid] * w3c;   // own column: no race
#pragma unroll
        for (int off = 16; off; off >>= 1) v += __shfl_down_sync(0xFFFFFFFFu, v, off);
        if (lane == 0) red[m * 8 + wid] = v;
    }
    __syncthreads();
    if (tid < ROWS) {
        float s = b3[0];
#pragma unroll
        for (int w = 0; w < 8; w++) s += red[tid * 8 + w];
        const int row = row0 + tid;
        if (row < NATOMS) out[row] = s;
    }
}

// ---------------------------------------------------------------------------
extern "C" void kernel_launch(void* const* d_in, const int* in_sizes, int n_in,
                              void* d_out, int out_size)
{
    const float* x   = (const float*)d_in[0];
    const float* rbf = (const float*)d_in[1];
    const int    nE  = in_sizes[0] / CCH;

    // `num_atoms` is a bare Python int in the reference; it may or may not be
    // materialized as a device input. Detect via element count (scalar == 1).
    int p = 2;
    if (in_sizes[2] == 1) p = 3;           // skip num_atoms scalar if present

    const int*   eidx  = (const int*)d_in[p + 0];   // int32 (JAX x64 disabled)
    const float* w_rbf = (const float*)d_in[p + 1];
    const float* b_rbf = (const float*)d_in[p + 2];
    const float* w1    = (const float*)d_in[p + 3];
    const float* b1    = (const float*)d_in[p + 4];
    const float* w2    = (const float*)d_in[p + 5];
    const float* b2    = (const float*)d_in[p + 6];
    const float* w3    = (const float*)d_in[p + 7];
    const float* b3    = (const float*)d_in[p + 8];
    float*       out   = (float*)d_out;

    const int n4 = NATOMS_PAD * CCH / 4;
    zero_kernel<<<(n4 + 255) / 256, 256>>>();

    scatter_kernel<<<1184, 256>>>(x, rbf, eidx, w_rbf, b_rbf, nE);

    const size_t smem_bytes = (size_t)(ROWS * 256 + 256 * WS_STRIDE) * sizeof(float); // ~100 KB
    cudaFuncSetAttribute(mlp_kernel, cudaFuncAttributeMaxDynamicSharedMemorySize,
                         (int)smem_bytes);
    mlp_kernel<<<NATOMS_PAD / ROWS, 256, smem_bytes>>>(w1, b1, w2, b2, w3, b3, out);
}

// round 13
// speedup vs baseline: 1.0148x; 1.0147x over previous
#include <cuda_runtime.h>
#include <cstdint>

#define E_EDGES     300000
#define NATOMS      10000
#define NATOMS_PAD  10016
#define CCH         256
#define RBFD        16
#define ROWS        32
#define WS_STRIDE   66

// Per-atom accumulator scratch (padded rows stay zero so the last MLP block reads zeros)
__device__ float g_accum[NATOMS_PAD * CCH];

__device__ __forceinline__ unsigned long long fma2(unsigned long long a,
                                                   unsigned long long b,
                                                   unsigned long long c) {
    unsigned long long d;
    asm("fma.rn.f32x2 %0, %1, %2, %3;" : "=l"(d) : "l"(a), "l"(b), "l"(c));
    return d;
}

__device__ __forceinline__ float hadd2(unsigned long long a) {
    float lo, hi;
    asm("mov.b64 {%0, %1}, %2;" : "=f"(lo), "=f"(hi) : "l"(a));
    return lo + hi;
}

// ---------------------------------------------------------------------------
// Kernel 0: zero the accumulator
// ---------------------------------------------------------------------------
__global__ void zero_kernel() {
    int i = blockIdx.x * blockDim.x + threadIdx.x;
    const int n4 = NATOMS_PAD * CCH / 4;
    float4* p = reinterpret_cast<float4*>(g_accum);
    if (i < n4) p[i] = make_float4(0.f, 0.f, 0.f, 0.f);
}

// ---------------------------------------------------------------------------
// Kernel 1: fused rbf-filter * x  +  scatter-add (red.v4.f32)
// Block = 256 threads = 4 edge-lanes (ey) x 64 channel-groups (cx, 4 ch each).
// W rows for this thread's 4 channels live in registers as f32x2 pairs.
// Edge index is read as INT32 (JAX without x64 downcasts int64 -> int32).
// ---------------------------------------------------------------------------
__global__ void __launch_bounds__(256) scatter_kernel(
    const float* __restrict__ x, const float* __restrict__ rbf,
    const int* __restrict__ eidx,
    const float* __restrict__ w_rbf, const float* __restrict__ b_rbf, int nE)
{
    const int tid = threadIdx.x;
    const int cx  = tid & 63;
    const int ey  = tid >> 6;
    const int c0  = cx * 4;

    // Load w_rbf rows for 4 channels as 8 f32x2 pairs each (pairs over RBF dim)
    unsigned long long w2[4][8];
#pragma unroll
    for (int j = 0; j < 4; j++) {
        const ulonglong2* wp = reinterpret_cast<const ulonglong2*>(w_rbf + (c0 + j) * RBFD);
        ulonglong2 q0 = wp[0], q1 = wp[1], q2 = wp[2], q3 = wp[3];
        w2[j][0] = q0.x; w2[j][1] = q0.y; w2[j][2] = q1.x; w2[j][3] = q1.y;
        w2[j][4] = q2.x; w2[j][5] = q2.y; w2[j][6] = q3.x; w2[j][7] = q3.y;
    }
    const float4 bv = *reinterpret_cast<const float4*>(b_rbf + c0);

    const int stride = gridDim.x * 4;
    for (int e = blockIdx.x * 4 + ey; e < nE; e += stride) {
        const int a = eidx[e];

        // rbf row: 16 floats = 8 f32x2 pairs (broadcast load across the 64 cx threads)
        const ulonglong2* rp = reinterpret_cast<const ulonglong2*>(rbf + (size_t)e * RBFD);
        ulonglong2 r0 = rp[0], r1 = rp[1], r2 = rp[2], r3 = rp[3];
        unsigned long long rf2[8] = {r0.x, r0.y, r1.x, r1.y, r2.x, r2.y, r3.x, r3.y};

        const float4 xv = *reinterpret_cast<const float4*>(x + (size_t)e * CCH + c0);

        unsigned long long a0 = 0ull, a1 = 0ull, a2 = 0ull, a3 = 0ull;
#pragma unroll
        for (int r = 0; r < 8; r++) {
            a0 = fma2(w2[0][r], rf2[r], a0);
            a1 = fma2(w2[1][r], rf2[r], a1);
            a2 = fma2(w2[2][r], rf2[r], a2);
            a3 = fma2(w2[3][r], rf2[r], a3);
        }
        const float m0 = (hadd2(a0) + bv.x) * xv.x;
        const float m1 = (hadd2(a1) + bv.y) * xv.y;
        const float m2 = (hadd2(a2) + bv.z) * xv.z;
        const float m3 = (hadd2(a3) + bv.w) * xv.w;

        if (a >= 0 && a < NATOMS) {   // defensive: never fault, surface rel_err instead
            float* dst = g_accum + (size_t)a * CCH + c0;
            asm volatile("red.global.add.v4.f32 [%0], {%1, %2, %3, %4};"
                         :: "l"(dst), "f"(m0), "f"(m1), "f"(m2), "f"(m3) : "memory");
        }
    }
}

// ---------------------------------------------------------------------------
// Kernel 2: fused 3-layer MLP. One block = 32 rows x 256 cols.
// Thread owns one output column; accumulates 32 rows with f32x2 over K-pairs.
// Weight k-tiles staged through smem (stride 66 -> 8B aligned, <=2-way conflict).
// h1/h2 live in smem (a_s is reused in place).
// ---------------------------------------------------------------------------
__device__ __forceinline__ void gemm_silu_layer(
    float* a_s, float* ws,
    const float* __restrict__ wglob, const float* __restrict__ bias, int c)
{
    unsigned long long acc[ROWS];
#pragma unroll
    for (int m = 0; m < ROWS; m++) acc[m] = 0ull;

    const int tid = threadIdx.x;
    for (int kt = 0; kt < 4; kt++) {
        __syncthreads();
        {   // stage W tile [256 x 64] -> ws[cr*66 + kk]
            const int cr0 = tid >> 4;
            const int kk4 = (tid & 15) << 2;
#pragma unroll
            for (int p = 0; p < 16; p++) {
                const int cr = cr0 + p * 16;
                const float4 v = *reinterpret_cast<const float4*>(wglob + cr * 256 + kt * 64 + kk4);
                float* d = ws + cr * WS_STRIDE + kk4;
                d[0] = v.x; d[1] = v.y; d[2] = v.z; d[3] = v.w;
            }
        }
        __syncthreads();

        const float* abase0 = a_s + kt * 64;
#pragma unroll 1
        for (int k2 = 0; k2 < 32; k2++) {
            const unsigned long long wp =
                *reinterpret_cast<const unsigned long long*>(ws + c * WS_STRIDE + 2 * k2);
            const float* ab = abase0 + 2 * k2;
#pragma unroll
            for (int m = 0; m < ROWS; m++) {
                const unsigned long long ap =
                    *reinterpret_cast<const unsigned long long*>(ab + m * 256);
                acc[m] = fma2(wp, ap, acc[m]);
            }
        }
    }
    __syncthreads();  // all reads of a_s / ws done before overwriting a_s

    const float bc = bias[c];
#pragma unroll
    for (int m = 0; m < ROWS; m++) {
        float v = hadd2(acc[m]) + bc;
        v = v / (1.0f + __expf(-v));   // SiLU
        a_s[m * 256 + c] = v;
    }
}

__global__ void __launch_bounds__(256) mlp_kernel(
    const float* __restrict__ w1, const float* __restrict__ b1,
    const float* __restrict__ w2, const float* __restrict__ b2,
    const float* __restrict__ w3, const float* __restrict__ b3,
    float* __restrict__ out)
{
    extern __shared__ float smem[];
    float* a_s = smem;                 // 32*256 floats
    float* ws  = smem + ROWS * 256;    // 256*66 floats

    const int tid  = threadIdx.x;
    const int row0 = blockIdx.x * ROWS;

    // stage input rows (padded accumulator rows are zero)
    {
        const float4* src = reinterpret_cast<const float4*>(g_accum + (size_t)row0 * 256);
        float4* dst = reinterpret_cast<float4*>(a_s);
#pragma unroll
        for (int i = 0; i < 8; i++) dst[i * 256 + tid] = src[i * 256 + tid];
    }
    // gemm_silu_layer starts with __syncthreads(), covering the staging barrier.
    gemm_silu_layer(a_s, ws, w1, b1, tid);
    gemm_silu_layer(a_s, ws, w2, b2, tid);

    // layer 3: y[m] = dot(h2[m,:], w3) + b3
    const float w3c = w3[tid];
    float* red = ws;                   // ws reads are done (sync inside layer 2)
    const int lane = tid & 31, wid = tid >> 5;
#pragma unroll
    for (int m = 0; m < ROWS; m++) {
        float v = a_s[m * 256 + tid] * w3c;   // own column: no race
#pragma unroll
        for (int off = 16; off; off >>= 1) v += __shfl_down_sync(0xFFFFFFFFu, v, off);
        if (lane == 0) red[m * 8 + wid] = v;
    }
    __syncthreads();
    if (tid < ROWS) {
        float s = b3[0];
#pragma unroll
        for (int w = 0; w < 8; w++) s += red[tid * 8 + w];
        const int row = row0 + tid;
        if (row < NATOMS) out[row] = s;
    }
}

// ---------------------------------------------------------------------------
extern "C" void kernel_launch(void* const* d_in, const int* in_sizes, int n_in,
                              void* d_out, int out_size)
{
    const float* x   = (const float*)d_in[0];
    const float* rbf = (const float*)d_in[1];
    const int    nE  = in_sizes[0] / CCH;

    // `num_atoms` is a bare Python int in the reference; it may or may not be
    // materialized as a device input. Detect via element count (scalar == 1).
    int p = 2;
    if (in_sizes[2] == 1) p = 3;           // skip num_atoms scalar if present

    const int*   eidx  = (const int*)d_in[p + 0];   // int32 (JAX x64 disabled)
    const float* w_rbf = (const float*)d_in[p + 1];
    const float* b_rbf = (const float*)d_in[p + 2];
    const float* w1    = (const float*)d_in[p + 3];
    const float* b1    = (const float*)d_in[p + 4];
    const float* w2    = (const float*)d_in[p + 5];
    const float* b2    = (const float*)d_in[p + 6];
    const float* w3    = (const float*)d_in[p + 7];
    const float* b3    = (const float*)d_in[p + 8];
    float*       out   = (float*)d_out;

    const int n4 = NATOMS_PAD * CCH / 4;
    zero_kernel<<<(n4 + 255) / 256, 256>>>();

    scatter_kernel<<<1184, 256>>>(x, rbf, eidx, w_rbf, b_rbf, nE);

    const size_t smem_bytes = (size_t)(ROWS * 256 + 256 * WS_STRIDE) * sizeof(float); // ~100 KB
    cudaFuncSetAttribute(mlp_kernel, cudaFuncAttributeMaxDynamicSharedMemorySize,
                         (int)smem_bytes);
    mlp_kernel<<<NATOMS_PAD / ROWS, 256, smem_bytes>>>(w1, b1, w2, b2, w3, b3, out);
}

// round 14
// speedup vs baseline: 1.0184x; 1.0036x over previous
#include <cuda_runtime.h>
#include <cstdint>

#define E_EDGES     300000
#define NATOMS      10000
#define NATOMS_PAD  10016
#define CCH         256
#define RBFD        16
#define ROWS        32
#define WS_STRIDE   66

// Per-atom accumulator scratch (padded rows stay zero so the last MLP block reads zeros)
__device__ float g_accum[NATOMS_PAD * CCH];

__device__ __forceinline__ unsigned long long fma2(unsigned long long a,
                                                   unsigned long long b,
                                                   unsigned long long c) {
    unsigned long long d;
    asm("fma.rn.f32x2 %0, %1, %2, %3;" : "=l"(d) : "l"(a), "l"(b), "l"(c));
    return d;
}

__device__ __forceinline__ float hadd2(unsigned long long a) {
    float lo, hi;
    asm("mov.b64 {%0, %1}, %2;" : "=f"(lo), "=f"(hi) : "l"(a));
    return lo + hi;
}

// ---------------------------------------------------------------------------
// Kernel 0: zero the accumulator
// ---------------------------------------------------------------------------
__global__ void zero_kernel() {
    int i = blockIdx.x * blockDim.x + threadIdx.x;
    const int n4 = NATOMS_PAD * CCH / 4;
    float4* p = reinterpret_cast<float4*>(g_accum);
    if (i < n4) p[i] = make_float4(0.f, 0.f, 0.f, 0.f);
}

// ---------------------------------------------------------------------------
// Kernel 1: fused rbf-filter * x  +  scatter-add (red.v4.f32)
// Block = 256 threads = 4 edge-lanes (ey) x 64 channel-groups (cx, 4 ch each).
// W rows for this thread's 4 channels live in registers as f32x2 pairs.
// Edge index is read as INT32 (JAX without x64 downcasts int64 -> int32).
// ---------------------------------------------------------------------------
__global__ void __launch_bounds__(256) scatter_kernel(
    const float* __restrict__ x, const float* __restrict__ rbf,
    const int* __restrict__ eidx,
    const float* __restrict__ w_rbf, const float* __restrict__ b_rbf, int nE)
{
    const int tid = threadIdx.x;
    const int cx  = tid & 63;
    const int ey  = tid >> 6;
    const int c0  = cx * 4;

    // Load w_rbf rows for 4 channels as 8 f32x2 pairs each (pairs over RBF dim)
    unsigned long long w2[4][8];
#pragma unroll
    for (int j = 0; j < 4; j++) {
        const ulonglong2* wp = reinterpret_cast<const ulonglong2*>(w_rbf + (c0 + j) * RBFD);
        ulonglong2 q0 = wp[0], q1 = wp[1], q2 = wp[2], q3 = wp[3];
        w2[j][0] = q0.x; w2[j][1] = q0.y; w2[j][2] = q1.x; w2[j][3] = q1.y;
        w2[j][4] = q2.x; w2[j][5] = q2.y; w2[j][6] = q3.x; w2[j][7] = q3.y;
    }
    const float4 bv = *reinterpret_cast<const float4*>(b_rbf + c0);

    const int stride = gridDim.x * 4;
    for (int e = blockIdx.x * 4 + ey; e < nE; e += stride) {
        const int a = eidx[e];

        // rbf row: 16 floats = 8 f32x2 pairs (broadcast load across the 64 cx threads)
        const ulonglong2* rp = reinterpret_cast<const ulonglong2*>(rbf + (size_t)e * RBFD);
        ulonglong2 r0 = rp[0], r1 = rp[1], r2 = rp[2], r3 = rp[3];
        unsigned long long rf2[8] = {r0.x, r0.y, r1.x, r1.y, r2.x, r2.y, r3.x, r3.y};

        const float4 xv = *reinterpret_cast<const float4*>(x + (size_t)e * CCH + c0);

        unsigned long long a0 = 0ull, a1 = 0ull, a2 = 0ull, a3 = 0ull;
#pragma unroll
        for (int r = 0; r < 8; r++) {
            a0 = fma2(w2[0][r], rf2[r], a0);
            a1 = fma2(w2[1][r], rf2[r], a1);
            a2 = fma2(w2[2][r], rf2[r], a2);
            a3 = fma2(w2[3][r], rf2[r], a3);
        }
        const float m0 = (hadd2(a0) + bv.x) * xv.x;
        const float m1 = (hadd2(a1) + bv.y) * xv.y;
        const float m2 = (hadd2(a2) + bv.z) * xv.z;
        const float m3 = (hadd2(a3) + bv.w) * xv.w;

        if (a >= 0 && a < NATOMS) {   // defensive: never fault, surface rel_err instead
            float* dst = g_accum + (size_t)a * CCH + c0;
            asm volatile("red.global.add.v4.f32 [%0], {%1, %2, %3, %4};"
                         :: "l"(dst), "f"(m0), "f"(m1), "f"(m2), "f"(m3) : "memory");
        }
    }
}

// ---------------------------------------------------------------------------
// Kernel 2: fused 3-layer MLP. One block = 32 rows x 256 cols.
// Thread owns one output column; accumulates 32 rows with f32x2 over K-pairs.
// Weight k-tiles staged through smem (stride 66 -> 8B aligned, <=2-way conflict).
// h1/h2 live in smem (a_s is reused in place).
// ---------------------------------------------------------------------------
__device__ __forceinline__ void gemm_silu_layer(
    float* a_s, float* ws,
    const float* __restrict__ wglob, const float* __restrict__ bias, int c)
{
    unsigned long long acc[ROWS];
#pragma unroll
    for (int m = 0; m < ROWS; m++) acc[m] = 0ull;

    const int tid = threadIdx.x;
    for (int kt = 0; kt < 4; kt++) {
        __syncthreads();
        {   // stage W tile [256 x 64] -> ws[cr*66 + kk]
            const int cr0 = tid >> 4;
            const int kk4 = (tid & 15) << 2;
#pragma unroll
            for (int p = 0; p < 16; p++) {
                const int cr = cr0 + p * 16;
                const float4 v = *reinterpret_cast<const float4*>(wglob + cr * 256 + kt * 64 + kk4);
                float* d = ws + cr * WS_STRIDE + kk4;
                d[0] = v.x; d[1] = v.y; d[2] = v.z; d[3] = v.w;
            }
        }
        __syncthreads();

        const float* abase0 = a_s + kt * 64;
#pragma unroll 1
        for (int k2 = 0; k2 < 32; k2++) {
            const unsigned long long wp =
                *reinterpret_cast<const unsigned long long*>(ws + c * WS_STRIDE + 2 * k2);
            const float* ab = abase0 + 2 * k2;
#pragma unroll
            for (int m = 0; m < ROWS; m++) {
                const unsigned long long ap =
                    *reinterpret_cast<const unsigned long long*>(ab + m * 256);
                acc[m] = fma2(wp, ap, acc[m]);
            }
        }
    }
    __syncthreads();  // all reads of a_s / ws done before overwriting a_s

    const float bc = bias[c];
#pragma unroll
    for (int m = 0; m < ROWS; m++) {
        float v = hadd2(acc[m]) + bc;
        v = v / (1.0f + __expf(-v));   // SiLU
        a_s[m * 256 + c] = v;
    }
}

__global__ void __launch_bounds__(256) mlp_kernel(
    const float* __restrict__ w1, const float* __restrict__ b1,
    const float* __restrict__ w2, const float* __restrict__ b2,
    const float* __restrict__ w3, const float* __restrict__ b3,
    float* __restrict__ out)
{
    extern __shared__ float smem[];
    float* a_s = smem;                 // 32*256 floats
    float* ws  = smem + ROWS * 256;    // 256*66 floats

    const int tid  = threadIdx.x;
    const int row0 = blockIdx.x * ROWS;

    // stage input rows (padded accumulator rows are zero)
    {
        const float4* src = reinterpret_cast<const float4*>(g_accum + (size_t)row0 * 256);
        float4* dst = reinterpret_cast<float4*>(a_s);
#pragma unroll
        for (int i = 0; i < 8; i++) dst[i * 256 + tid] = src[i * 256 + tid];
    }
    // gemm_silu_layer starts with __syncthreads(), covering the staging barrier.
    gemm_silu_layer(a_s, ws, w1, b1, tid);
    gemm_silu_layer(a_s, ws, w2, b2, tid);

    // layer 3: y[m] = dot(h2[m,:], w3) + b3
    const float w3c = w3[tid];
    float* red = ws;                   // ws reads are done (sync inside layer 2)
    const int lane = tid & 31, wid = tid >> 5;
#pragma unroll
    for (int m = 0; m < ROWS; m++) {
        float v = a_s[m * 256 + tid] * w3c;   // own column: no race
#pragma unroll
        for (int off = 16; off; off >>= 1) v += __shfl_down_sync(0xFFFFFFFFu, v, off);
        if (lane == 0) red[m * 8 + wid] = v;
    }
    __syncthreads();
    if (tid < ROWS) {
        float s = b3[0];
#pragma unroll
        for (int w = 0; w < 8; w++) s += red[tid * 8 + w];
        const int row = row0 + tid;
        if (row < NATOMS) out[row] = s;
    }
}

// ---------------------------------------------------------------------------
extern "C" void kernel_launch(void* const* d_in, const int* in_sizes, int n_in,
                              void* d_out, int out_size)
{
    const float* x   = (const float*)d_in[0];
    const float* rbf = (const float*)d_in[1];
    const int    nE  = in_sizes[0] / CCH;

    // `num_atoms` is a bare Python int in the reference; it may or may not be
    // materialized as a device input. Detect via element count (scalar == 1).
    int p = 2;
    if (in_sizes[2] == 1) p = 3;           // skip num_atoms scalar if present

    const int*   eidx  = (const int*)d_in[p + 0];   // int32 (JAX x64 disabled)
    const float* w_rbf = (const float*)d_in[p + 1];
    const float* b_rbf = (const float*)d_in[p + 2];
    const float* w1    = (const float*)d_in[p + 3];
    const float* b1    = (const float*)d_in[p + 4];
    const float* w2    = (const float*)d_in[p + 5];
    const float* b2    = (const float*)d_in[p + 6];
    const float* w3    = (const float*)d_in[p + 7];
    const float* b3    = (const float*)d_in[p + 8];
    float*       out   = (float*)d_out;

    const int n4 = NATOMS_PAD * CCH / 4;
    zero_kernel<<<(n4 + 255) / 256, 256>>>();

    scatter_kernel<<<1184, 256>>>(x, rbf, eidx, w_rbf, b_rbf, nE);

    const size_t smem_bytes = (size_t)(ROWS * 256 + 256 * WS_STRIDE) * sizeof(float); // ~100 KB
    cudaFuncSetAttribute(mlp_kernel, cudaFuncAttributeMaxDynamicSharedMemorySize,
                         (int)smem_bytes);
    mlp_kernel<<<NATOMS_PAD / ROWS, 256, smem_bytes>>>(w1, b1, w2, b2, w3, b3, out);
}